// round 10
// baseline (speedup 1.0000x reference)
#include <cuda_runtime.h>
#include <cuda_bf16.h>

#define N_NODES 100000
#define IN_F 64
#define E_MAX 1600000
#define NREP 8

// Scratch
__device__ int g_degR[NREP * N_NODES];   // replicated degree counters
__device__ int g_curR[NREP * N_NODES];   // replicated fill cursors
__device__ int g_deg[N_NODES];           // total degree
__device__ int g_off[N_NODES];           // CSR offsets
__device__ int g_eidx[E_MAX];            // src per edge, bucketed by dst
__device__ int g_partials[512];
__device__ float g_y[(size_t)N_NODES * 64];   // y = x @ W_lin^T (25.6MB)

// Grid barrier for the CSR role blocks (sense-reversing, replay-safe)
__device__ int g_bar_cnt;
__device__ volatile int g_bar_gen;

__device__ __forceinline__ void grid_bar(int nb) {
    __threadfence();
    __syncthreads();
    if (threadIdx.x == 0) {
        int gen = g_bar_gen;
        if (atomicAdd(&g_bar_cnt, 1) == nb - 1) {
            g_bar_cnt = 0;
            __threadfence();
            g_bar_gen = gen + 1;
        } else {
            while (g_bar_gen == gen) __nanosleep(32);
        }
    }
    __syncthreads();
}

// ---------------------------------------------------------------------------
// Packed f32x2 FMA (Blackwell FFMA2 — PTX only)
// ---------------------------------------------------------------------------
__device__ __forceinline__ unsigned long long fma_f32x2(unsigned long long a,
                                                        unsigned long long b,
                                                        unsigned long long c) {
    unsigned long long d;
    asm("fma.rn.f32x2 %0, %1, %2, %3;" : "=l"(d) : "l"(a), "l"(b), "l"(c));
    return d;
}
__device__ __forceinline__ unsigned long long pack_f32x2(float lo, float hi) {
    unsigned long long r;
    asm("mov.b64 %0, {%1, %2};" : "=l"(r) : "f"(lo), "f"(hi));
    return r;
}
__device__ __forceinline__ float sum_f32x2(unsigned long long v) {
    float lo, hi;
    asm("mov.b64 {%0, %1}, %2;" : "=f"(lo), "=f"(hi) : "l"(v));
    return lo + hi;
}

// ---------------------------------------------------------------------------
// K1 (mega): role-split. bid%3==2 -> CSR build (8-way replicated atomics);
// bid%3 in {0,1} -> GEMM: y = x@Wl^T, out = x@Ws^T + b. The two roles are
// independent and overlap (CSR is atomic/L2-bound, GEMM is FMA-bound).
// No join barrier: the following gather kernel launch is the sync point.
// ---------------------------------------------------------------------------
__global__ void __launch_bounds__(256, 3)
mega_kernel(const float* __restrict__ x,
            const int* __restrict__ src,
            const int* __restrict__ dst,
            const float* __restrict__ W_lin,
            const float* __restrict__ b_lin,
            const float* __restrict__ W_self,
            const float* __restrict__ b_self,
            const float* __restrict__ bias,
            float* __restrict__ out,
            int N, int E, int nseg, int ntiles) {
    __shared__ float sWl[64 * 64];   // GEMM [f4][o][4]; CSR aliases ints
    __shared__ float sWs[64 * 64];

    const int t = threadIdx.x;
    const int bid = blockIdx.x;
    const int grid = gridDim.x;
    const int nCSR = grid / 3;
    const int nGEMM = grid - nCSR;
    const int r3 = bid % 3;

    if (r3 == 2) {
        // ======================= CSR role =======================
        int ci = bid / 3;
        int* ib0 = (int*)sWl;
        int* ib1 = (int*)sWl + 512;
        const int r = (ci ^ (t >> 5)) & (NREP - 1);

        // zero replicated degree counters
        for (int i = ci * 256 + t; i < NREP * N; i += nCSR * 256)
            g_degR[i] = 0;
        grid_bar(nCSR);

        // count in-degrees into replica r
        {
            int* degr = g_degR + r * N;
            for (int e = ci * 256 + t; e < E; e += nCSR * 256) {
                int* p = degr + __ldg(dst + e);
                asm volatile("red.global.add.s32 [%0], 1;" :: "l"(p) : "memory");
            }
        }
        grid_bar(nCSR);

        // per-segment (256-wide) scans over total degree
        for (int s = ci; s < nseg; s += nCSR) {
            int i = s * 256 + t;
            int v = 0;
            if (i < N) {
                #pragma unroll
                for (int rr = 0; rr < NREP; rr++) v += g_degR[rr * N + i];
                g_deg[i] = v;
            }
            ib0[t] = v;
            __syncthreads();
            int* a = ib0; int* b = ib1;
            #pragma unroll
            for (int off = 1; off < 256; off <<= 1) {
                int sv = a[t];
                if (t >= off) sv += a[t - off];
                b[t] = sv;
                __syncthreads();
                int* tmp = a; a = b; b = tmp;
            }
            if (t == 255) g_partials[s] = a[255];
            if (i < N) g_off[i] = a[t] - v;   // exclusive within segment
            __syncthreads();
        }
        grid_bar(nCSR);

        // block ci==0: exclusive scan of nseg partials (nseg <= 512)
        if (ci == 0) {
            int v0 = (t < nseg) ? g_partials[t] : 0;
            int v1 = (t + 256 < nseg) ? g_partials[t + 256] : 0;
            ib0[t] = v0; ib0[t + 256] = v1;
            __syncthreads();
            int* a = ib0; int* b = ib1;
            #pragma unroll
            for (int off = 1; off < 512; off <<= 1) {
                int s0 = a[t];
                if (t >= off) s0 += a[t - off];
                int s1 = a[t + 256] + a[t + 256 - off];
                b[t] = s0; b[t + 256] = s1;
                __syncthreads();
                int* tmp = a; a = b; b = tmp;
            }
            if (t < nseg) g_partials[t] = a[t] - v0;
            if (t + 256 < nseg) g_partials[t + 256] = a[t + 256] - v1;
        }
        grid_bar(nCSR);

        // add segment bases; derive per-replica cursor bases
        for (int s = ci; s < nseg; s += nCSR) {
            int base = g_partials[s];
            int i = s * 256 + t;
            if (i < N) {
                int off = g_off[i] + base;
                g_off[i] = off;
                int c = off;
                #pragma unroll
                for (int rr = 0; rr < NREP; rr++) {
                    g_curR[rr * N + i] = c;
                    c += g_degR[rr * N + i];
                }
            }
        }
        grid_bar(nCSR);

        // fill buckets via replica-r cursor
        {
            int* curr = g_curR + r * N;
            for (int e = ci * 256 + t; e < E; e += nCSR * 256) {
                int d = __ldg(dst + e);
                int pos = atomicAdd(curr + d, 1);
                g_eidx[pos] = __ldg(src + e);
            }
        }
    } else {
        // ======================= GEMM role =======================
        int gi = (bid / 3) * 2 + r3;

        #pragma unroll
        for (int i = t; i < 64 * 64; i += 256) {
            int o = i >> 6;
            int f = i & 63;
            int dsti = (f >> 2) * 256 + o * 4 + (f & 3);
            sWl[dsti] = W_lin[i];
            sWs[dsti] = W_self[i];
        }
        __syncthreads();

        int o = t & 63;
        int g = t >> 6;
        float b = b_lin[o] + b_self[o] + bias[o];

        for (int tile = gi; tile < ntiles; tile += nGEMM) {
            int n0 = tile * 32 + g * 8;
            const float* __restrict__ xbase = x + (size_t)n0 * 64;

            if (n0 + 7 < N) {
                unsigned long long accY[8], accS[8];
                unsigned long long binit = pack_f32x2(b, 0.f);
                #pragma unroll
                for (int k = 0; k < 8; k++) { accY[k] = 0ull; accS[k] = binit; }

                #pragma unroll
                for (int f4 = 0; f4 < 16; f4++) {
                    ulonglong2 wl = *reinterpret_cast<const ulonglong2*>(
                                        &sWl[f4 * 256 + o * 4]);
                    ulonglong2 ws = *reinterpret_cast<const ulonglong2*>(
                                        &sWs[f4 * 256 + o * 4]);
                    #pragma unroll
                    for (int k = 0; k < 8; k++) {
                        ulonglong2 xv = *reinterpret_cast<const ulonglong2*>(
                                            xbase + k * 64 + f4 * 4);
                        accY[k] = fma_f32x2(xv.x, wl.x, accY[k]);
                        accY[k] = fma_f32x2(xv.y, wl.y, accY[k]);
                        accS[k] = fma_f32x2(xv.x, ws.x, accS[k]);
                        accS[k] = fma_f32x2(xv.y, ws.y, accS[k]);
                    }
                }
                float* yp = g_y + (size_t)n0 * 64 + o;
                float* op = out + (size_t)n0 * 64 + o;
                #pragma unroll
                for (int k = 0; k < 8; k++) {
                    yp[k * 64] = sum_f32x2(accY[k]);
                    op[k * 64] = sum_f32x2(accS[k]);
                }
            } else {
                for (int k = 0; k < 8; k++) {
                    int n = n0 + k;
                    if (n >= N) break;
                    float ay = 0.f, as = b;
                    for (int f = 0; f < 64; f++) {
                        float xv = xbase[k * 64 + f];
                        ay += xv * sWl[(f >> 2) * 256 + o * 4 + (f & 3)];
                        as += xv * sWs[(f >> 2) * 256 + o * 4 + (f & 3)];
                    }
                    g_y[(size_t)n * 64 + o] = ay;
                    out[(size_t)n * 64 + o] = as;
                }
            }
        }
    }
}

// ---------------------------------------------------------------------------
// K2 gather: out[n] += sum_{e: dst[e]=n} y[src[e]].
// WARP per node: sub-half 0 (lanes 0-15) takes even edges, sub-half 1 (lanes
// 16-31) takes odd edges; each lane owns one float4 of the row. 8-edge unroll
// -> 8 y-row loads in flight per warp (2x R9's MLP) at the SAME per-thread
// register count. Cross-half combine via shfl.xor 16.
// ---------------------------------------------------------------------------
__global__ void __launch_bounds__(256, 4)
gather_out_kernel(float* __restrict__ out, int N) {
    const float4* __restrict__ y4 = (const float4*)g_y;
    float4* __restrict__ out4 = (float4*)out;

    int gw = (blockIdx.x * 256 + threadIdx.x) >> 5;   // global warp = node
    if (gw >= N) return;
    int lane = threadIdx.x & 31;
    int sub = lane >> 4;       // 0 or 1
    int l = lane & 15;         // float4 chunk in row

    int beg = g_off[gw];
    int cnt = g_deg[gw];
    const int* __restrict__ ep = g_eidx + beg;

    float4 acc = make_float4(0.f, 0.f, 0.f, 0.f);

    int j = 0;
    for (; j + 8 <= cnt; j += 8) {
        int s0 = __ldg(ep + j + 0 + sub);
        int s1 = __ldg(ep + j + 2 + sub);
        int s2 = __ldg(ep + j + 4 + sub);
        int s3 = __ldg(ep + j + 6 + sub);
        float4 v0 = __ldg(y4 + (size_t)s0 * 16 + l);
        float4 v1 = __ldg(y4 + (size_t)s1 * 16 + l);
        float4 v2 = __ldg(y4 + (size_t)s2 * 16 + l);
        float4 v3 = __ldg(y4 + (size_t)s3 * 16 + l);
        acc.x += (v0.x + v1.x) + (v2.x + v3.x);
        acc.y += (v0.y + v1.y) + (v2.y + v3.y);
        acc.z += (v0.z + v1.z) + (v2.z + v3.z);
        acc.w += (v0.w + v1.w) + (v2.w + v3.w);
    }
    for (; j + 2 <= cnt; j += 2) {
        int s = __ldg(ep + j + sub);
        float4 v = __ldg(y4 + (size_t)s * 16 + l);
        acc.x += v.x; acc.y += v.y; acc.z += v.z; acc.w += v.w;
    }
    if (j < cnt && sub == 0) {
        int s = __ldg(ep + j);
        float4 v = __ldg(y4 + (size_t)s * 16 + l);
        acc.x += v.x; acc.y += v.y; acc.z += v.z; acc.w += v.w;
    }

    // combine the two halves (lane <-> lane^16)
    acc.x += __shfl_xor_sync(0xffffffffu, acc.x, 16);
    acc.y += __shfl_xor_sync(0xffffffffu, acc.y, 16);
    acc.z += __shfl_xor_sync(0xffffffffu, acc.z, 16);
    acc.w += __shfl_xor_sync(0xffffffffu, acc.w, 16);

    if (sub == 0) {
        size_t oidx = (size_t)gw * 16 + l;
        float4 cur = out4[oidx];
        cur.x += acc.x; cur.y += acc.y; cur.z += acc.z; cur.w += acc.w;
        out4[oidx] = cur;
    }
}

// ---------------------------------------------------------------------------
// Launch. Input order: x, src, dst, W_lin, b_lin, W_self, b_self, bias
// ---------------------------------------------------------------------------
extern "C" void kernel_launch(void* const* d_in, const int* in_sizes, int n_in,
                              void* d_out, int out_size) {
    const float* x      = (const float*)d_in[0];
    const int*   src    = (const int*)d_in[1];
    const int*   dst    = (const int*)d_in[2];
    const float* W_lin  = (const float*)d_in[3];
    const float* b_lin  = (const float*)d_in[4];
    const float* W_self = (const float*)d_in[5];
    const float* b_self = (const float*)d_in[6];
    const float* bias   = (const float*)d_in[7];
    float* out = (float*)d_out;

    int N = in_sizes[0] / IN_F;   // 100000
    int E = in_sizes[1];          // 1280000
    int nseg = (N + 255) / 256;   // 391 (<=512)
    int ntiles = (N + 31) / 32;   // 3125

    int dev = 0, sms = 148, occ = 3;
    cudaGetDevice(&dev);
    cudaDeviceGetAttribute(&sms, cudaDevAttrMultiProcessorCount, dev);
    cudaOccupancyMaxActiveBlocksPerMultiprocessor(&occ, mega_kernel, 256, 0);
    if (occ > 3) occ = 3;
    if (occ < 1) occ = 1;
    int grid = sms * occ;          // co-resident: grid_bar among CSR blocks safe
    if (grid < 3) grid = 3;

    mega_kernel<<<grid, 256>>>(x, src, dst, W_lin, b_lin, W_self, b_self,
                               bias, out, N, E, nseg, ntiles);

    // gather: one warp per node
    long long threads = (long long)N * 32;
    gather_out_kernel<<<(int)((threads + 255) / 256), 256>>>(out, N);
}

// round 11
// speedup vs baseline: 1.0596x; 1.0596x over previous
#include <cuda_runtime.h>
#include <cuda_bf16.h>

#define N_NODES 100000
#define IN_F 64
#define E_MAX 1600000
#define NREP 4
#define CHUNK_E 2048

// Scratch
__device__ int g_degR[NREP * N_NODES];   // replicated degree counters
__device__ int g_curR[NREP * N_NODES];   // replicated fill cursors
__device__ int g_off[N_NODES];           // CSR offsets
__device__ int g_eidx[E_MAX];            // src per edge, bucketed by dst
__device__ int g_partials[512];
__device__ float g_y[(size_t)N_NODES * 64];   // y = x @ W_lin^T (25.6MB)

// Grid barrier (sense-reversing, replay-safe)
__device__ int g_bar_cnt;
__device__ volatile int g_bar_gen;

__device__ __forceinline__ void grid_bar(int nb) {
    __threadfence();
    __syncthreads();
    if (threadIdx.x == 0) {
        int gen = g_bar_gen;
        if (atomicAdd(&g_bar_cnt, 1) == nb - 1) {
            g_bar_cnt = 0;
            __threadfence();
            g_bar_gen = gen + 1;
        } else {
            while (g_bar_gen == gen) __nanosleep(32);
        }
    }
    __syncthreads();
}

// ---------------------------------------------------------------------------
// Packed f32x2 FMA (Blackwell FFMA2 — PTX only)
// ---------------------------------------------------------------------------
__device__ __forceinline__ unsigned long long fma_f32x2(unsigned long long a,
                                                        unsigned long long b,
                                                        unsigned long long c) {
    unsigned long long d;
    asm("fma.rn.f32x2 %0, %1, %2, %3;" : "=l"(d) : "l"(a), "l"(b), "l"(c));
    return d;
}
__device__ __forceinline__ unsigned long long pack_f32x2(float lo, float hi) {
    unsigned long long r;
    asm("mov.b64 %0, {%1, %2};" : "=l"(r) : "f"(lo), "f"(hi));
    return r;
}
__device__ __forceinline__ float sum_f32x2(unsigned long long v) {
    float lo, hi;
    asm("mov.b64 {%0, %1}, %2;" : "=f"(lo), "=f"(hi) : "l"(v));
    return lo + hi;
}

__device__ __forceinline__ void red_add1(int* p) {
    asm volatile("red.global.add.s32 [%0], 1;" :: "l"(p) : "memory");
}

// ---------------------------------------------------------------------------
// K1: persistent CSR build. int4-vectorized count/fill (4 edges per LDG.128,
// 4 independent atomics in flight). 4-way replicated counters: replica
// r = (bid ^ (t>>5)) & 3 identical in count and fill so slots line up.
// ---------------------------------------------------------------------------
__global__ void __launch_bounds__(256)
csr_build_kernel(const int* __restrict__ src,
                 const int* __restrict__ dst,
                 int N, int E, int nseg) {
    __shared__ int ib0[512];
    __shared__ int ib1[512];

    const int t = threadIdx.x;
    const int bid = blockIdx.x;
    const int grid = gridDim.x;
    const int r = (bid ^ (t >> 5)) & (NREP - 1);
    const int E4 = E >> 2;

    // zero replicated degree counters (int4 stores)
    {
        int4* z4 = (int4*)g_degR;
        int n4 = (NREP * N) >> 2;
        int4 zero = make_int4(0, 0, 0, 0);
        for (int i = bid * 256 + t; i < n4; i += grid * 256) z4[i] = zero;
        // tail
        for (int i = (n4 << 2) + bid * 256 + t; i < NREP * N; i += grid * 256)
            g_degR[i] = 0;
    }
    grid_bar(grid);

    // count in-degrees into replica r (int4 loads, 4 independent reds)
    {
        int* degr = g_degR + r * N;
        const int4* dst4 = (const int4*)dst;
        for (int q = bid * 256 + t; q < E4; q += grid * 256) {
            int4 d = __ldg(dst4 + q);
            red_add1(degr + d.x);
            red_add1(degr + d.y);
            red_add1(degr + d.z);
            red_add1(degr + d.w);
        }
        for (int e = (E4 << 2) + bid * 256 + t; e < E; e += grid * 256)
            red_add1(degr + __ldg(dst + e));
    }
    grid_bar(grid);

    // per-segment (256-wide) scans over total degree
    for (int s = bid; s < nseg; s += grid) {
        int i = s * 256 + t;
        int v = 0;
        if (i < N) {
            #pragma unroll
            for (int rr = 0; rr < NREP; rr++) v += g_degR[rr * N + i];
        }
        ib0[t] = v;
        __syncthreads();
        int* a = ib0; int* b = ib1;
        #pragma unroll
        for (int off = 1; off < 256; off <<= 1) {
            int sv = a[t];
            if (t >= off) sv += a[t - off];
            b[t] = sv;
            __syncthreads();
            int* tmp = a; a = b; b = tmp;
        }
        if (t == 255) g_partials[s] = a[255];
        if (i < N) g_off[i] = a[t] - v;   // exclusive within segment
        __syncthreads();
    }
    grid_bar(grid);

    // block 0: exclusive scan of nseg partials (nseg <= 512)
    if (bid == 0) {
        int v0 = (t < nseg) ? g_partials[t] : 0;
        int v1 = (t + 256 < nseg) ? g_partials[t + 256] : 0;
        ib0[t] = v0; ib0[t + 256] = v1;
        __syncthreads();
        int* a = ib0; int* b = ib1;
        #pragma unroll
        for (int off = 1; off < 512; off <<= 1) {
            int s0 = a[t];
            if (t >= off) s0 += a[t - off];
            int s1 = a[t + 256] + a[t + 256 - off];
            b[t] = s0; b[t + 256] = s1;
            __syncthreads();
            int* tmp = a; a = b; b = tmp;
        }
        if (t < nseg) g_partials[t] = a[t] - v0;
        if (t + 256 < nseg) g_partials[t + 256] = a[t + 256] - v1;
    }
    grid_bar(grid);

    // add segment bases; derive per-replica cursor bases
    for (int s = bid; s < nseg; s += grid) {
        int base = g_partials[s];
        int i = s * 256 + t;
        if (i < N) {
            int off = g_off[i] + base;
            g_off[i] = off;
            int c = off;
            #pragma unroll
            for (int rr = 0; rr < NREP; rr++) {
                g_curR[rr * N + i] = c;
                c += g_degR[rr * N + i];
            }
        }
    }
    grid_bar(grid);

    // fill buckets via replica-r cursor (int4 loads of dst and src)
    {
        int* curr = g_curR + r * N;
        const int4* dst4 = (const int4*)dst;
        const int4* src4 = (const int4*)src;
        for (int q = bid * 256 + t; q < E4; q += grid * 256) {
            int4 d = __ldg(dst4 + q);
            int4 s = __ldg(src4 + q);
            int p0 = atomicAdd(curr + d.x, 1);
            int p1 = atomicAdd(curr + d.y, 1);
            int p2 = atomicAdd(curr + d.z, 1);
            int p3 = atomicAdd(curr + d.w, 1);
            g_eidx[p0] = s.x;
            g_eidx[p1] = s.y;
            g_eidx[p2] = s.z;
            g_eidx[p3] = s.w;
        }
        for (int e = (E4 << 2) + bid * 256 + t; e < E; e += grid * 256) {
            int d = __ldg(dst + e);
            int pos = atomicAdd(curr + d, 1);
            g_eidx[pos] = __ldg(src + e);
        }
    }
}

// ---------------------------------------------------------------------------
// K2: y = x @ W_lin^T ; out = x @ W_self^T + b
// ---------------------------------------------------------------------------
__global__ void __launch_bounds__(256, 3)
gemm_kernel(const float* __restrict__ x,
            const float* __restrict__ W_lin,
            const float* __restrict__ b_lin,
            const float* __restrict__ W_self,
            const float* __restrict__ b_self,
            const float* __restrict__ bias,
            float* __restrict__ out,
            int N, int ntiles) {
    __shared__ float sWl[64 * 64];   // [f4][o][4]
    __shared__ float sWs[64 * 64];

    const int t = threadIdx.x;

    #pragma unroll
    for (int i = t; i < 64 * 64; i += 256) {
        int o = i >> 6;
        int f = i & 63;
        int dsti = (f >> 2) * 256 + o * 4 + (f & 3);
        sWl[dsti] = W_lin[i];
        sWs[dsti] = W_self[i];
    }
    __syncthreads();

    int o = t & 63;
    int g = t >> 6;
    float b = b_lin[o] + b_self[o] + bias[o];

    for (int tile = blockIdx.x; tile < ntiles; tile += gridDim.x) {
        int n0 = tile * 32 + g * 8;
        const float* __restrict__ xbase = x + (size_t)n0 * 64;

        if (n0 + 7 < N) {
            unsigned long long accY[8], accS[8];
            unsigned long long binit = pack_f32x2(b, 0.f);
            #pragma unroll
            for (int k = 0; k < 8; k++) { accY[k] = 0ull; accS[k] = binit; }

            #pragma unroll
            for (int f4 = 0; f4 < 16; f4++) {
                ulonglong2 wl = *reinterpret_cast<const ulonglong2*>(
                                    &sWl[f4 * 256 + o * 4]);
                ulonglong2 ws = *reinterpret_cast<const ulonglong2*>(
                                    &sWs[f4 * 256 + o * 4]);
                #pragma unroll
                for (int k = 0; k < 8; k++) {
                    ulonglong2 xv = *reinterpret_cast<const ulonglong2*>(
                                        xbase + k * 64 + f4 * 4);
                    accY[k] = fma_f32x2(xv.x, wl.x, accY[k]);
                    accY[k] = fma_f32x2(xv.y, wl.y, accY[k]);
                    accS[k] = fma_f32x2(xv.x, ws.x, accS[k]);
                    accS[k] = fma_f32x2(xv.y, ws.y, accS[k]);
                }
            }
            float* yp = g_y + (size_t)n0 * 64 + o;
            float* op = out + (size_t)n0 * 64 + o;
            #pragma unroll
            for (int k = 0; k < 8; k++) {
                yp[k * 64] = sum_f32x2(accY[k]);
                op[k * 64] = sum_f32x2(accS[k]);
            }
        } else {
            for (int k = 0; k < 8; k++) {
                int n = n0 + k;
                if (n >= N) break;
                float ay = 0.f, as = b;
                for (int f = 0; f < 64; f++) {
                    float xv = xbase[k * 64 + f];
                    ay += xv * sWl[(f >> 2) * 256 + o * 4 + (f & 3)];
                    as += xv * sWs[(f >> 2) * 256 + o * 4 + (f & 3)];
                }
                g_y[(size_t)n * 64 + o] = ay;
                out[(size_t)n * 64 + o] = as;
            }
        }
    }
}

// ---------------------------------------------------------------------------
// K3: gather: out[n] += sum_{e: dst[e]=n} y[src[e]].
// Block = 16 nodes (16 threads each). The block's edges are CONTIGUOUS in
// g_eidx (CSR) -> stage them coalesced into smem, then the per-edge chain is
// LDS(29cyc) -> LDG(y) instead of LDG -> LDG: dependent depth halved.
// ---------------------------------------------------------------------------
__global__ void __launch_bounds__(256, 4)
gather_out_kernel(float* __restrict__ out, int N, int E) {
    __shared__ int se[CHUNK_E];

    const float4* __restrict__ y4 = (const float4*)g_y;
    float4* __restrict__ out4 = (float4*)out;

    int n0 = blockIdx.x * 16;
    if (n0 >= N) return;
    int t = threadIdx.x;
    int nl = t >> 4;
    int l = t & 15;
    int node = n0 + nl;
    bool valid = (node < N);

    int eblk_beg = g_off[n0];
    int n_end = n0 + 16;
    int eblk_end = (n_end < N) ? g_off[n_end] : E;

    int mybeg = 0, myend = 0;
    if (valid) {
        mybeg = g_off[node];
        myend = (node + 1 < N) ? g_off[node + 1] : E;
    }

    float4 a0 = make_float4(0.f, 0.f, 0.f, 0.f);
    float4 a1 = a0;

    for (int cs = eblk_beg; cs < eblk_end; cs += CHUNK_E) {
        int ce = cs + CHUNK_E;
        if (ce > eblk_end) ce = eblk_end;

        // stage edge srcs coalesced
        for (int i = cs + t; i < ce; i += 256) se[i - cs] = g_eidx[i];
        __syncthreads();

        int lo = (mybeg > cs) ? mybeg : cs;
        int hi = (myend < ce) ? myend : ce;
        int j = lo;
        for (; j + 4 <= hi; j += 4) {
            int s0 = se[j - cs + 0];
            int s1 = se[j - cs + 1];
            int s2 = se[j - cs + 2];
            int s3 = se[j - cs + 3];
            float4 v0 = __ldg(y4 + (size_t)s0 * 16 + l);
            float4 v1 = __ldg(y4 + (size_t)s1 * 16 + l);
            float4 v2 = __ldg(y4 + (size_t)s2 * 16 + l);
            float4 v3 = __ldg(y4 + (size_t)s3 * 16 + l);
            a0.x += v0.x; a0.y += v0.y; a0.z += v0.z; a0.w += v0.w;
            a1.x += v1.x; a1.y += v1.y; a1.z += v1.z; a1.w += v1.w;
            a0.x += v2.x; a0.y += v2.y; a0.z += v2.z; a0.w += v2.w;
            a1.x += v3.x; a1.y += v3.y; a1.z += v3.z; a1.w += v3.w;
        }
        for (; j < hi; j++) {
            int s = se[j - cs];
            float4 v = __ldg(y4 + (size_t)s * 16 + l);
            a0.x += v.x; a0.y += v.y; a0.z += v.z; a0.w += v.w;
        }
        __syncthreads();
    }

    if (valid) {
        size_t oidx = (size_t)node * 16 + l;
        float4 cur = out4[oidx];
        cur.x += a0.x + a1.x;
        cur.y += a0.y + a1.y;
        cur.z += a0.z + a1.z;
        cur.w += a0.w + a1.w;
        out4[oidx] = cur;
    }
}

// ---------------------------------------------------------------------------
// Launch. Input order: x, src, dst, W_lin, b_lin, W_self, b_self, bias
// ---------------------------------------------------------------------------
extern "C" void kernel_launch(void* const* d_in, const int* in_sizes, int n_in,
                              void* d_out, int out_size) {
    const float* x      = (const float*)d_in[0];
    const int*   src    = (const int*)d_in[1];
    const int*   dst    = (const int*)d_in[2];
    const float* W_lin  = (const float*)d_in[3];
    const float* b_lin  = (const float*)d_in[4];
    const float* W_self = (const float*)d_in[5];
    const float* b_self = (const float*)d_in[6];
    const float* bias   = (const float*)d_in[7];
    float* out = (float*)d_out;

    int N = in_sizes[0] / IN_F;   // 100000
    int E = in_sizes[1];          // 1280000
    int nseg = (N + 255) / 256;   // 391 (<=512)
    int ntiles = (N + 31) / 32;   // 3125

    int dev = 0, sms = 148, occ1 = 4;
    cudaGetDevice(&dev);
    cudaDeviceGetAttribute(&sms, cudaDevAttrMultiProcessorCount, dev);

    // K1: persistent CSR build — deadlock-safe grid
    cudaOccupancyMaxActiveBlocksPerMultiprocessor(&occ1, csr_build_kernel, 256, 0);
    if (occ1 > 4) occ1 = 4;
    if (occ1 < 1) occ1 = 1;
    int g1 = sms * occ1;
    csr_build_kernel<<<g1, 256>>>(src, dst, N, E, nseg);

    // K2: GEMM
    int g2 = sms * 3;
    if (g2 > ntiles) g2 = ntiles;
    gemm_kernel<<<g2, 256>>>(x, W_lin, b_lin, W_self, b_self, bias, out,
                             N, ntiles);

    // K3: gather (16 nodes per block)
    int g3 = (N + 15) / 16;
    gather_out_kernel<<<g3, 256>>>(out, N, E);
}

// round 12
// speedup vs baseline: 1.2731x; 1.2015x over previous
#include <cuda_runtime.h>
#include <cuda_bf16.h>

#define N_NODES 100000
#define IN_F 64
#define SLOTS 64
#define OV_MAX 4096

// Scratch
__device__ int g_cnt[N_NODES];                    // per-node fill count
__device__ int g_slot[(size_t)N_NODES * SLOTS];   // bucketed src ids (25.6MB)
__device__ int g_ov_cnt;
__device__ int g_ov_dst[OV_MAX];
__device__ int g_ov_src[OV_MAX];
__device__ float g_y[(size_t)N_NODES * 64];       // y = x @ W_lin^T (25.6MB)

// Grid barrier (sense-reversing, replay-safe: cnt returns to 0, gen grows)
__device__ int g_bar_cnt;
__device__ volatile int g_bar_gen;

__device__ __forceinline__ void grid_bar(int nb) {
    __threadfence();
    __syncthreads();
    if (threadIdx.x == 0) {
        int gen = g_bar_gen;
        if (atomicAdd(&g_bar_cnt, 1) == nb - 1) {
            g_bar_cnt = 0;
            __threadfence();
            g_bar_gen = gen + 1;
        } else {
            while (g_bar_gen == gen) __nanosleep(32);
        }
    }
    __syncthreads();
}

// ---------------------------------------------------------------------------
// Packed f32x2 FMA (Blackwell FFMA2 — PTX only)
// ---------------------------------------------------------------------------
__device__ __forceinline__ unsigned long long fma_f32x2(unsigned long long a,
                                                        unsigned long long b,
                                                        unsigned long long c) {
    unsigned long long d;
    asm("fma.rn.f32x2 %0, %1, %2, %3;" : "=l"(d) : "l"(a), "l"(b), "l"(c));
    return d;
}
__device__ __forceinline__ unsigned long long pack_f32x2(float lo, float hi) {
    unsigned long long r;
    asm("mov.b64 %0, {%1, %2};" : "=l"(r) : "f"(lo), "f"(hi));
    return r;
}
__device__ __forceinline__ float sum_f32x2(unsigned long long v) {
    float lo, hi;
    asm("mov.b64 {%0, %1}, %2;" : "=f"(lo), "=f"(hi) : "l"(v));
    return lo + hi;
}

// ---------------------------------------------------------------------------
// K1: zero counters, then single-pass bucket fill (int4 edge loads).
// No scans, no offsets: slot base = dst * 64. Overflow -> side list.
// ---------------------------------------------------------------------------
__global__ void __launch_bounds__(256)
bucket_fill_kernel(const int* __restrict__ src,
                   const int* __restrict__ dst,
                   int N, int E) {
    const int t = threadIdx.x;
    const int bid = blockIdx.x;
    const int grid = gridDim.x;

    // zero counts (int4) + overflow cursor
    {
        int4* z4 = (int4*)g_cnt;
        int n4 = N >> 2;
        int4 zero = make_int4(0, 0, 0, 0);
        for (int i = bid * 256 + t; i < n4; i += grid * 256) z4[i] = zero;
        for (int i = (n4 << 2) + bid * 256 + t; i < N; i += grid * 256)
            g_cnt[i] = 0;
        if (bid == 0 && t == 0) g_ov_cnt = 0;
    }
    grid_bar(grid);

    // single fill pass: 4 edges per int4 load, 4 independent atomics
    const int E4 = E >> 2;
    const int4* dst4 = (const int4*)dst;
    const int4* src4 = (const int4*)src;
    for (int q = bid * 256 + t; q < E4; q += grid * 256) {
        int4 d = __ldg(dst4 + q);
        int4 s = __ldg(src4 + q);
        int p0 = atomicAdd(g_cnt + d.x, 1);
        int p1 = atomicAdd(g_cnt + d.y, 1);
        int p2 = atomicAdd(g_cnt + d.z, 1);
        int p3 = atomicAdd(g_cnt + d.w, 1);
        if (p0 < SLOTS) g_slot[(size_t)d.x * SLOTS + p0] = s.x;
        else { int o = atomicAdd(&g_ov_cnt, 1); if (o < OV_MAX) { g_ov_dst[o] = d.x; g_ov_src[o] = s.x; } }
        if (p1 < SLOTS) g_slot[(size_t)d.y * SLOTS + p1] = s.y;
        else { int o = atomicAdd(&g_ov_cnt, 1); if (o < OV_MAX) { g_ov_dst[o] = d.y; g_ov_src[o] = s.y; } }
        if (p2 < SLOTS) g_slot[(size_t)d.z * SLOTS + p2] = s.z;
        else { int o = atomicAdd(&g_ov_cnt, 1); if (o < OV_MAX) { g_ov_dst[o] = d.z; g_ov_src[o] = s.z; } }
        if (p3 < SLOTS) g_slot[(size_t)d.w * SLOTS + p3] = s.w;
        else { int o = atomicAdd(&g_ov_cnt, 1); if (o < OV_MAX) { g_ov_dst[o] = d.w; g_ov_src[o] = s.w; } }
    }
    for (int e = (E4 << 2) + bid * 256 + t; e < E; e += grid * 256) {
        int d = __ldg(dst + e);
        int s = __ldg(src + e);
        int p = atomicAdd(g_cnt + d, 1);
        if (p < SLOTS) g_slot[(size_t)d * SLOTS + p] = s;
        else { int o = atomicAdd(&g_ov_cnt, 1); if (o < OV_MAX) { g_ov_dst[o] = d; g_ov_src[o] = s; } }
    }
}

// ---------------------------------------------------------------------------
// K2: y = x @ W_lin^T ; out = x @ W_self^T + b
// ---------------------------------------------------------------------------
__global__ void __launch_bounds__(256, 3)
gemm_kernel(const float* __restrict__ x,
            const float* __restrict__ W_lin,
            const float* __restrict__ b_lin,
            const float* __restrict__ W_self,
            const float* __restrict__ b_self,
            const float* __restrict__ bias,
            float* __restrict__ out,
            int N, int ntiles) {
    __shared__ float sWl[64 * 64];   // [f4][o][4]
    __shared__ float sWs[64 * 64];

    const int t = threadIdx.x;

    #pragma unroll
    for (int i = t; i < 64 * 64; i += 256) {
        int o = i >> 6;
        int f = i & 63;
        int dsti = (f >> 2) * 256 + o * 4 + (f & 3);
        sWl[dsti] = W_lin[i];
        sWs[dsti] = W_self[i];
    }
    __syncthreads();

    int o = t & 63;
    int g = t >> 6;
    float b = b_lin[o] + b_self[o] + bias[o];

    for (int tile = blockIdx.x; tile < ntiles; tile += gridDim.x) {
        int n0 = tile * 32 + g * 8;
        const float* __restrict__ xbase = x + (size_t)n0 * 64;

        if (n0 + 7 < N) {
            unsigned long long accY[8], accS[8];
            unsigned long long binit = pack_f32x2(b, 0.f);
            #pragma unroll
            for (int k = 0; k < 8; k++) { accY[k] = 0ull; accS[k] = binit; }

            #pragma unroll
            for (int f4 = 0; f4 < 16; f4++) {
                ulonglong2 wl = *reinterpret_cast<const ulonglong2*>(
                                    &sWl[f4 * 256 + o * 4]);
                ulonglong2 ws = *reinterpret_cast<const ulonglong2*>(
                                    &sWs[f4 * 256 + o * 4]);
                #pragma unroll
                for (int k = 0; k < 8; k++) {
                    ulonglong2 xv = *reinterpret_cast<const ulonglong2*>(
                                        xbase + k * 64 + f4 * 4);
                    accY[k] = fma_f32x2(xv.x, wl.x, accY[k]);
                    accY[k] = fma_f32x2(xv.y, wl.y, accY[k]);
                    accS[k] = fma_f32x2(xv.x, ws.x, accS[k]);
                    accS[k] = fma_f32x2(xv.y, ws.y, accS[k]);
                }
            }
            float* yp = g_y + (size_t)n0 * 64 + o;
            float* op = out + (size_t)n0 * 64 + o;
            #pragma unroll
            for (int k = 0; k < 8; k++) {
                yp[k * 64] = sum_f32x2(accY[k]);
                op[k * 64] = sum_f32x2(accS[k]);
            }
        } else {
            for (int k = 0; k < 8; k++) {
                int n = n0 + k;
                if (n >= N) break;
                float ay = 0.f, as = b;
                for (int f = 0; f < 64; f++) {
                    float xv = xbase[k * 64 + f];
                    ay += xv * sWl[(f >> 2) * 256 + o * 4 + (f & 3)];
                    as += xv * sWs[(f >> 2) * 256 + o * 4 + (f & 3)];
                }
                g_y[(size_t)n * 64 + o] = ay;
                out[(size_t)n * 64 + o] = as;
            }
        }
    }
}

// ---------------------------------------------------------------------------
// K3: gather: out[n] += sum_slots y[slot[n][j]] (+ overflow entries).
// 16 threads/node. Indices come 4-at-a-time from ONE broadcast LDG.128 on the
// node's contiguous 256B slot line, prefetched one round ahead; 4 independent
// y-row loads in flight.
// ---------------------------------------------------------------------------
__global__ void __launch_bounds__(256, 4)
gather_out_kernel(float* __restrict__ out, int N) {
    const float4* __restrict__ y4 = (const float4*)g_y;
    float4* __restrict__ out4 = (float4*)out;

    int idx = blockIdx.x * 256 + threadIdx.x;
    int node = idx >> 4;
    if (node >= N) return;
    int l = idx & 15;

    int c = g_cnt[node];
    if (c > SLOTS) c = SLOTS;
    const int4* __restrict__ sp =
        (const int4*)(g_slot + (size_t)node * SLOTS);

    float4 a0 = make_float4(0.f, 0.f, 0.f, 0.f);
    float4 a1 = a0;

    int j = 0;
    int4 i4 = (c > 0) ? __ldg(sp) : make_int4(0, 0, 0, 0);
    for (; j + 4 <= c; j += 4) {
        int4 nx = (j + 4 < c) ? __ldg(sp + (j >> 2) + 1) : i4;
        float4 v0 = __ldg(y4 + (size_t)i4.x * 16 + l);
        float4 v1 = __ldg(y4 + (size_t)i4.y * 16 + l);
        float4 v2 = __ldg(y4 + (size_t)i4.z * 16 + l);
        float4 v3 = __ldg(y4 + (size_t)i4.w * 16 + l);
        a0.x += v0.x; a0.y += v0.y; a0.z += v0.z; a0.w += v0.w;
        a1.x += v1.x; a1.y += v1.y; a1.z += v1.z; a1.w += v1.w;
        a0.x += v2.x; a0.y += v2.y; a0.z += v2.z; a0.w += v2.w;
        a1.x += v3.x; a1.y += v3.y; a1.z += v3.z; a1.w += v3.w;
        i4 = nx;
    }
    // tail (0..3 edges) using the prefetched i4
    int rem = c - j;
    if (rem > 0) {
        float4 v = __ldg(y4 + (size_t)i4.x * 16 + l);
        a0.x += v.x; a0.y += v.y; a0.z += v.z; a0.w += v.w;
    }
    if (rem > 1) {
        float4 v = __ldg(y4 + (size_t)i4.y * 16 + l);
        a1.x += v.x; a1.y += v.y; a1.z += v.z; a1.w += v.w;
    }
    if (rem > 2) {
        float4 v = __ldg(y4 + (size_t)i4.z * 16 + l);
        a0.x += v.x; a0.y += v.y; a0.z += v.z; a0.w += v.w;
    }

    // overflow entries (expected 0): broadcast scan
    int oc = g_ov_cnt;
    if (oc > OV_MAX) oc = OV_MAX;
    for (int k = 0; k < oc; k++) {
        if (g_ov_dst[k] == node) {
            int s = g_ov_src[k];
            float4 v = __ldg(y4 + (size_t)s * 16 + l);
            a0.x += v.x; a0.y += v.y; a0.z += v.z; a0.w += v.w;
        }
    }

    size_t oidx = (size_t)node * 16 + l;
    float4 cur = out4[oidx];
    cur.x += a0.x + a1.x;
    cur.y += a0.y + a1.y;
    cur.z += a0.z + a1.z;
    cur.w += a0.w + a1.w;
    out4[oidx] = cur;
}

// ---------------------------------------------------------------------------
// Launch. Input order: x, src, dst, W_lin, b_lin, W_self, b_self, bias
// ---------------------------------------------------------------------------
extern "C" void kernel_launch(void* const* d_in, const int* in_sizes, int n_in,
                              void* d_out, int out_size) {
    const float* x      = (const float*)d_in[0];
    const int*   src    = (const int*)d_in[1];
    const int*   dst    = (const int*)d_in[2];
    const float* W_lin  = (const float*)d_in[3];
    const float* b_lin  = (const float*)d_in[4];
    const float* W_self = (const float*)d_in[5];
    const float* b_self = (const float*)d_in[6];
    const float* bias   = (const float*)d_in[7];
    float* out = (float*)d_out;

    int N = in_sizes[0] / IN_F;   // 100000
    int E = in_sizes[1];          // 1280000
    int ntiles = (N + 31) / 32;   // 3125

    int dev = 0, sms = 148, occ1 = 4;
    cudaGetDevice(&dev);
    cudaDeviceGetAttribute(&sms, cudaDevAttrMultiProcessorCount, dev);

    // K1: zero + single-pass bucket fill (deadlock-safe persistent grid)
    cudaOccupancyMaxActiveBlocksPerMultiprocessor(&occ1, bucket_fill_kernel,
                                                  256, 0);
    if (occ1 > 4) occ1 = 4;
    if (occ1 < 1) occ1 = 1;
    bucket_fill_kernel<<<sms * occ1, 256>>>(src, dst, N, E);

    // K2: GEMM
    int g2 = sms * 3;
    if (g2 > ntiles) g2 = ntiles;
    gemm_kernel<<<g2, 256>>>(x, W_lin, b_lin, W_self, b_self, bias, out,
                             N, ntiles);

    // K3: gather (16 threads per node)
    long long gt = (long long)N * 16;
    gather_out_kernel<<<(int)((gt + 255) / 256), 256>>>(out, N);
}

// round 13
// speedup vs baseline: 1.3718x; 1.0775x over previous
#include <cuda_runtime.h>
#include <cuda_fp16.h>
#include <cuda_bf16.h>

#define N_NODES 100000
#define IN_F 64
#define SLOTS 64
#define OV_MAX 4096

// Scratch
__device__ int g_cnt[N_NODES];                    // per-node fill count
__device__ int g_slot[(size_t)N_NODES * SLOTS];   // bucketed src ids (25.6MB)
__device__ int g_ov_cnt;
__device__ int g_ov_dst[OV_MAX];
__device__ int g_ov_src[OV_MAX];
__device__ __half g_yh[(size_t)N_NODES * 64];     // y = x @ W_lin^T in fp16 (12.8MB)

// Grid barrier (sense-reversing, replay-safe)
__device__ int g_bar_cnt;
__device__ volatile int g_bar_gen;

__device__ __forceinline__ void grid_bar(int nb) {
    __threadfence();
    __syncthreads();
    if (threadIdx.x == 0) {
        int gen = g_bar_gen;
        if (atomicAdd(&g_bar_cnt, 1) == nb - 1) {
            g_bar_cnt = 0;
            __threadfence();
            g_bar_gen = gen + 1;
        } else {
            while (g_bar_gen == gen) __nanosleep(32);
        }
    }
    __syncthreads();
}

// ---------------------------------------------------------------------------
// Packed f32x2 FMA (Blackwell FFMA2 — PTX only)
// ---------------------------------------------------------------------------
__device__ __forceinline__ unsigned long long fma_f32x2(unsigned long long a,
                                                        unsigned long long b,
                                                        unsigned long long c) {
    unsigned long long d;
    asm("fma.rn.f32x2 %0, %1, %2, %3;" : "=l"(d) : "l"(a), "l"(b), "l"(c));
    return d;
}
__device__ __forceinline__ unsigned long long pack_f32x2(float lo, float hi) {
    unsigned long long r;
    asm("mov.b64 %0, {%1, %2};" : "=l"(r) : "f"(lo), "f"(hi));
    return r;
}
__device__ __forceinline__ float sum_f32x2(unsigned long long v) {
    float lo, hi;
    asm("mov.b64 {%0, %1}, %2;" : "=f"(lo), "=f"(hi) : "l"(v));
    return lo + hi;
}

// ---------------------------------------------------------------------------
// K1: zero counters, then single-pass bucket fill (int4 edge loads).
// ---------------------------------------------------------------------------
__global__ void __launch_bounds__(256)
bucket_fill_kernel(const int* __restrict__ src,
                   const int* __restrict__ dst,
                   int N, int E) {
    const int t = threadIdx.x;
    const int bid = blockIdx.x;
    const int grid = gridDim.x;

    // zero counts (int4) + overflow cursor
    {
        int4* z4 = (int4*)g_cnt;
        int n4 = N >> 2;
        int4 zero = make_int4(0, 0, 0, 0);
        for (int i = bid * 256 + t; i < n4; i += grid * 256) z4[i] = zero;
        for (int i = (n4 << 2) + bid * 256 + t; i < N; i += grid * 256)
            g_cnt[i] = 0;
        if (bid == 0 && t == 0) g_ov_cnt = 0;
    }
    grid_bar(grid);

    // single fill pass
    const int E4 = E >> 2;
    const int4* dst4 = (const int4*)dst;
    const int4* src4 = (const int4*)src;
    for (int q = bid * 256 + t; q < E4; q += grid * 256) {
        int4 d = __ldg(dst4 + q);
        int4 s = __ldg(src4 + q);
        int p0 = atomicAdd(g_cnt + d.x, 1);
        int p1 = atomicAdd(g_cnt + d.y, 1);
        int p2 = atomicAdd(g_cnt + d.z, 1);
        int p3 = atomicAdd(g_cnt + d.w, 1);
        if (p0 < SLOTS) g_slot[(size_t)d.x * SLOTS + p0] = s.x;
        else { int o = atomicAdd(&g_ov_cnt, 1); if (o < OV_MAX) { g_ov_dst[o] = d.x; g_ov_src[o] = s.x; } }
        if (p1 < SLOTS) g_slot[(size_t)d.y * SLOTS + p1] = s.y;
        else { int o = atomicAdd(&g_ov_cnt, 1); if (o < OV_MAX) { g_ov_dst[o] = d.y; g_ov_src[o] = s.y; } }
        if (p2 < SLOTS) g_slot[(size_t)d.z * SLOTS + p2] = s.z;
        else { int o = atomicAdd(&g_ov_cnt, 1); if (o < OV_MAX) { g_ov_dst[o] = d.z; g_ov_src[o] = s.z; } }
        if (p3 < SLOTS) g_slot[(size_t)d.w * SLOTS + p3] = s.w;
        else { int o = atomicAdd(&g_ov_cnt, 1); if (o < OV_MAX) { g_ov_dst[o] = d.w; g_ov_src[o] = s.w; } }
    }
    for (int e = (E4 << 2) + bid * 256 + t; e < E; e += grid * 256) {
        int d = __ldg(dst + e);
        int s = __ldg(src + e);
        int p = atomicAdd(g_cnt + d, 1);
        if (p < SLOTS) g_slot[(size_t)d * SLOTS + p] = s;
        else { int o = atomicAdd(&g_ov_cnt, 1); if (o < OV_MAX) { g_ov_dst[o] = d; g_ov_src[o] = s; } }
    }
}

// ---------------------------------------------------------------------------
// K2: y = x @ W_lin^T (stored fp16) ; out = x @ W_self^T + b (fp32)
// ---------------------------------------------------------------------------
__global__ void __launch_bounds__(256, 3)
gemm_kernel(const float* __restrict__ x,
            const float* __restrict__ W_lin,
            const float* __restrict__ b_lin,
            const float* __restrict__ W_self,
            const float* __restrict__ b_self,
            const float* __restrict__ bias,
            float* __restrict__ out,
            int N, int ntiles) {
    __shared__ float sWl[64 * 64];   // [f4][o][4]
    __shared__ float sWs[64 * 64];

    const int t = threadIdx.x;

    #pragma unroll
    for (int i = t; i < 64 * 64; i += 256) {
        int o = i >> 6;
        int f = i & 63;
        int dsti = (f >> 2) * 256 + o * 4 + (f & 3);
        sWl[dsti] = W_lin[i];
        sWs[dsti] = W_self[i];
    }
    __syncthreads();

    int o = t & 63;
    int g = t >> 6;
    float b = b_lin[o] + b_self[o] + bias[o];

    for (int tile = blockIdx.x; tile < ntiles; tile += gridDim.x) {
        int n0 = tile * 32 + g * 8;
        const float* __restrict__ xbase = x + (size_t)n0 * 64;

        if (n0 + 7 < N) {
            unsigned long long accY[8], accS[8];
            unsigned long long binit = pack_f32x2(b, 0.f);
            #pragma unroll
            for (int k = 0; k < 8; k++) { accY[k] = 0ull; accS[k] = binit; }

            #pragma unroll
            for (int f4 = 0; f4 < 16; f4++) {
                ulonglong2 wl = *reinterpret_cast<const ulonglong2*>(
                                    &sWl[f4 * 256 + o * 4]);
                ulonglong2 ws = *reinterpret_cast<const ulonglong2*>(
                                    &sWs[f4 * 256 + o * 4]);
                #pragma unroll
                for (int k = 0; k < 8; k++) {
                    ulonglong2 xv = *reinterpret_cast<const ulonglong2*>(
                                        xbase + k * 64 + f4 * 4);
                    accY[k] = fma_f32x2(xv.x, wl.x, accY[k]);
                    accY[k] = fma_f32x2(xv.y, wl.y, accY[k]);
                    accS[k] = fma_f32x2(xv.x, ws.x, accS[k]);
                    accS[k] = fma_f32x2(xv.y, ws.y, accS[k]);
                }
            }
            __half* yp = g_yh + (size_t)n0 * 64 + o;
            float* op = out + (size_t)n0 * 64 + o;
            #pragma unroll
            for (int k = 0; k < 8; k++) {
                yp[k * 64] = __float2half_rn(sum_f32x2(accY[k]));
                op[k * 64] = sum_f32x2(accS[k]);
            }
        } else {
            for (int k = 0; k < 8; k++) {
                int n = n0 + k;
                if (n >= N) break;
                float ay = 0.f, as = b;
                for (int f = 0; f < 64; f++) {
                    float xv = xbase[k * 64 + f];
                    ay += xv * sWl[(f >> 2) * 256 + o * 4 + (f & 3)];
                    as += xv * sWs[(f >> 2) * 256 + o * 4 + (f & 3)];
                }
                g_yh[(size_t)n * 64 + o] = __float2half_rn(ay);
                out[(size_t)n * 64 + o] = as;
            }
        }
    }
}

// ---------------------------------------------------------------------------
// K3: gather: out[n] += sum_slots y[slot[n][j]] (+ overflow), y in fp16.
// 16 threads/node; lane l loads 8B (4 halves = features 4l..4l+3) per row:
// row = 128B (half the fp32 traffic). Accumulate fp32. Slot indices come
// 4-at-a-time via one broadcast LDG.128, prefetched a round ahead.
// ---------------------------------------------------------------------------
__global__ void __launch_bounds__(256, 4)
gather_out_kernel(float* __restrict__ out, int N) {
    const uint2* __restrict__ yh2 = (const uint2*)g_yh;   // 8B = 4 halves
    float4* __restrict__ out4 = (float4*)out;

    int idx = blockIdx.x * 256 + threadIdx.x;
    int node = idx >> 4;
    if (node >= N) return;
    int l = idx & 15;

    int c = g_cnt[node];
    if (c > SLOTS) c = SLOTS;
    const int4* __restrict__ sp =
        (const int4*)(g_slot + (size_t)node * SLOTS);

    float4 a0 = make_float4(0.f, 0.f, 0.f, 0.f);
    float4 a1 = a0;

    int j = 0;
    int4 i4 = (c > 0) ? __ldg(sp) : make_int4(0, 0, 0, 0);
    for (; j + 4 <= c; j += 4) {
        int4 nx = (j + 4 < c) ? __ldg(sp + (j >> 2) + 1) : i4;
        uint2 u0 = __ldg(yh2 + (size_t)i4.x * 16 + l);
        uint2 u1 = __ldg(yh2 + (size_t)i4.y * 16 + l);
        uint2 u2 = __ldg(yh2 + (size_t)i4.z * 16 + l);
        uint2 u3 = __ldg(yh2 + (size_t)i4.w * 16 + l);

        float2 f0a = __half22float2(*(__half2*)&u0.x);
        float2 f0b = __half22float2(*(__half2*)&u0.y);
        float2 f1a = __half22float2(*(__half2*)&u1.x);
        float2 f1b = __half22float2(*(__half2*)&u1.y);
        float2 f2a = __half22float2(*(__half2*)&u2.x);
        float2 f2b = __half22float2(*(__half2*)&u2.y);
        float2 f3a = __half22float2(*(__half2*)&u3.x);
        float2 f3b = __half22float2(*(__half2*)&u3.y);

        a0.x += f0a.x + f2a.x; a0.y += f0a.y + f2a.y;
        a0.z += f0b.x + f2b.x; a0.w += f0b.y + f2b.y;
        a1.x += f1a.x + f3a.x; a1.y += f1a.y + f3a.y;
        a1.z += f1b.x + f3b.x; a1.w += f1b.y + f3b.y;
        i4 = nx;
    }
    // tail (0..3 edges) using the prefetched i4
    int rem = c - j;
    if (rem > 0) {
        uint2 u = __ldg(yh2 + (size_t)i4.x * 16 + l);
        float2 fa = __half22float2(*(__half2*)&u.x);
        float2 fb = __half22float2(*(__half2*)&u.y);
        a0.x += fa.x; a0.y += fa.y; a0.z += fb.x; a0.w += fb.y;
    }
    if (rem > 1) {
        uint2 u = __ldg(yh2 + (size_t)i4.y * 16 + l);
        float2 fa = __half22float2(*(__half2*)&u.x);
        float2 fb = __half22float2(*(__half2*)&u.y);
        a1.x += fa.x; a1.y += fa.y; a1.z += fb.x; a1.w += fb.y;
    }
    if (rem > 2) {
        uint2 u = __ldg(yh2 + (size_t)i4.z * 16 + l);
        float2 fa = __half22float2(*(__half2*)&u.x);
        float2 fb = __half22float2(*(__half2*)&u.y);
        a0.x += fa.x; a0.y += fa.y; a0.z += fb.x; a0.w += fb.y;
    }

    // overflow entries (expected 0)
    int oc = g_ov_cnt;
    if (oc > OV_MAX) oc = OV_MAX;
    for (int k = 0; k < oc; k++) {
        if (g_ov_dst[k] == node) {
            int s = g_ov_src[k];
            uint2 u = __ldg(yh2 + (size_t)s * 16 + l);
            float2 fa = __half22float2(*(__half2*)&u.x);
            float2 fb = __half22float2(*(__half2*)&u.y);
            a0.x += fa.x; a0.y += fa.y; a0.z += fb.x; a0.w += fb.y;
        }
    }

    size_t oidx = (size_t)node * 16 + l;
    float4 cur = out4[oidx];
    cur.x += a0.x + a1.x;
    cur.y += a0.y + a1.y;
    cur.z += a0.z + a1.z;
    cur.w += a0.w + a1.w;
    out4[oidx] = cur;
}

// ---------------------------------------------------------------------------
// Launch. Input order: x, src, dst, W_lin, b_lin, W_self, b_self, bias
// ---------------------------------------------------------------------------
extern "C" void kernel_launch(void* const* d_in, const int* in_sizes, int n_in,
                              void* d_out, int out_size) {
    const float* x      = (const float*)d_in[0];
    const int*   src    = (const int*)d_in[1];
    const int*   dst    = (const int*)d_in[2];
    const float* W_lin  = (const float*)d_in[3];
    const float* b_lin  = (const float*)d_in[4];
    const float* W_self = (const float*)d_in[5];
    const float* b_self = (const float*)d_in[6];
    const float* bias   = (const float*)d_in[7];
    float* out = (float*)d_out;

    int N = in_sizes[0] / IN_F;   // 100000
    int E = in_sizes[1];          // 1280000
    int ntiles = (N + 31) / 32;   // 3125

    int dev = 0, sms = 148, occ1 = 4;
    cudaGetDevice(&dev);
    cudaDeviceGetAttribute(&sms, cudaDevAttrMultiProcessorCount, dev);

    // K1: zero + single-pass bucket fill (only one grid barrier -> allow 8/SM)
    cudaOccupancyMaxActiveBlocksPerMultiprocessor(&occ1, bucket_fill_kernel,
                                                  256, 0);
    if (occ1 > 8) occ1 = 8;
    if (occ1 < 1) occ1 = 1;
    bucket_fill_kernel<<<sms * occ1, 256>>>(src, dst, N, E);

    // K2: GEMM
    int g2 = sms * 3;
    if (g2 > ntiles) g2 = ntiles;
    gemm_kernel<<<g2, 256>>>(x, W_lin, b_lin, W_self, b_self, bias, out,
                             N, ntiles);

    // K3: gather (16 threads per node)
    long long gt = (long long)N * 16;
    gather_out_kernel<<<(int)((gt + 255) / 256), 256>>>(out, N);
}

// round 14
// speedup vs baseline: 1.4279x; 1.0409x over previous
#include <cuda_runtime.h>
#include <cuda_fp16.h>
#include <cuda_bf16.h>

#define N_NODES 100000
#define IN_F 64
#define SLOTS 64
#define OV_MAX 4096

// Scratch
__device__ int g_cnt[N_NODES];                    // per-node fill count
__device__ int g_slot[(size_t)N_NODES * SLOTS];   // bucketed src ids (25.6MB)
__device__ int g_ov_cnt;
__device__ int g_ov_dst[OV_MAX];
__device__ int g_ov_src[OV_MAX];
__device__ __half g_yh[(size_t)N_NODES * 64];     // y = x @ W_lin^T, fp16 (12.8MB)

// Grid barrier (sense-reversing, replay-safe)
__device__ int g_bar_cnt;
__device__ volatile int g_bar_gen;

__device__ __forceinline__ void grid_bar(int nb) {
    __threadfence();
    __syncthreads();
    if (threadIdx.x == 0) {
        int gen = g_bar_gen;
        if (atomicAdd(&g_bar_cnt, 1) == nb - 1) {
            g_bar_cnt = 0;
            __threadfence();
            g_bar_gen = gen + 1;
        } else {
            while (g_bar_gen == gen) __nanosleep(32);
        }
    }
    __syncthreads();
}

// ---------------------------------------------------------------------------
// Packed f32x2 FMA (Blackwell FFMA2 — PTX only)
// ---------------------------------------------------------------------------
__device__ __forceinline__ unsigned long long fma_f32x2(unsigned long long a,
                                                        unsigned long long b,
                                                        unsigned long long c) {
    unsigned long long d;
    asm("fma.rn.f32x2 %0, %1, %2, %3;" : "=l"(d) : "l"(a), "l"(b), "l"(c));
    return d;
}
__device__ __forceinline__ unsigned long long pack_f32x2(float lo, float hi) {
    unsigned long long r;
    asm("mov.b64 %0, {%1, %2};" : "=l"(r) : "f"(lo), "f"(hi));
    return r;
}
__device__ __forceinline__ float sum_f32x2(unsigned long long v) {
    float lo, hi;
    asm("mov.b64 {%0, %1}, %2;" : "=f"(lo), "=f"(hi) : "l"(v));
    return lo + hi;
}

// ---------------------------------------------------------------------------
// K1: zero counters, then single-pass bucket fill (int4 edge loads).
// ---------------------------------------------------------------------------
__global__ void __launch_bounds__(256)
bucket_fill_kernel(const int* __restrict__ src,
                   const int* __restrict__ dst,
                   int N, int E) {
    const int t = threadIdx.x;
    const int bid = blockIdx.x;
    const int grid = gridDim.x;

    // zero counts (int4) + overflow cursor
    {
        int4* z4 = (int4*)g_cnt;
        int n4 = N >> 2;
        int4 zero = make_int4(0, 0, 0, 0);
        for (int i = bid * 256 + t; i < n4; i += grid * 256) z4[i] = zero;
        for (int i = (n4 << 2) + bid * 256 + t; i < N; i += grid * 256)
            g_cnt[i] = 0;
        if (bid == 0 && t == 0) g_ov_cnt = 0;
    }
    grid_bar(grid);

    // single fill pass
    const int E4 = E >> 2;
    const int4* dst4 = (const int4*)dst;
    const int4* src4 = (const int4*)src;
    for (int q = bid * 256 + t; q < E4; q += grid * 256) {
        int4 d = __ldg(dst4 + q);
        int4 s = __ldg(src4 + q);
        int p0 = atomicAdd(g_cnt + d.x, 1);
        int p1 = atomicAdd(g_cnt + d.y, 1);
        int p2 = atomicAdd(g_cnt + d.z, 1);
        int p3 = atomicAdd(g_cnt + d.w, 1);
        if (p0 < SLOTS) g_slot[(size_t)d.x * SLOTS + p0] = s.x;
        else { int o = atomicAdd(&g_ov_cnt, 1); if (o < OV_MAX) { g_ov_dst[o] = d.x; g_ov_src[o] = s.x; } }
        if (p1 < SLOTS) g_slot[(size_t)d.y * SLOTS + p1] = s.y;
        else { int o = atomicAdd(&g_ov_cnt, 1); if (o < OV_MAX) { g_ov_dst[o] = d.y; g_ov_src[o] = s.y; } }
        if (p2 < SLOTS) g_slot[(size_t)d.z * SLOTS + p2] = s.z;
        else { int o = atomicAdd(&g_ov_cnt, 1); if (o < OV_MAX) { g_ov_dst[o] = d.z; g_ov_src[o] = s.z; } }
        if (p3 < SLOTS) g_slot[(size_t)d.w * SLOTS + p3] = s.w;
        else { int o = atomicAdd(&g_ov_cnt, 1); if (o < OV_MAX) { g_ov_dst[o] = d.w; g_ov_src[o] = s.w; } }
    }
    for (int e = (E4 << 2) + bid * 256 + t; e < E; e += grid * 256) {
        int d = __ldg(dst + e);
        int s = __ldg(src + e);
        int p = atomicAdd(g_cnt + d, 1);
        if (p < SLOTS) g_slot[(size_t)d * SLOTS + p] = s;
        else { int o = atomicAdd(&g_ov_cnt, 1); if (o < OV_MAX) { g_ov_dst[o] = d; g_ov_src[o] = s; } }
    }
}

// ---------------------------------------------------------------------------
// K2: y = x @ W_lin^T (stored fp16) ; out = x @ W_self^T + b (fp32)
// ---------------------------------------------------------------------------
__global__ void __launch_bounds__(256, 3)
gemm_kernel(const float* __restrict__ x,
            const float* __restrict__ W_lin,
            const float* __restrict__ b_lin,
            const float* __restrict__ W_self,
            const float* __restrict__ b_self,
            const float* __restrict__ bias,
            float* __restrict__ out,
            int N, int ntiles) {
    __shared__ float sWl[64 * 64];   // [f4][o][4]
    __shared__ float sWs[64 * 64];

    const int t = threadIdx.x;

    #pragma unroll
    for (int i = t; i < 64 * 64; i += 256) {
        int o = i >> 6;
        int f = i & 63;
        int dsti = (f >> 2) * 256 + o * 4 + (f & 3);
        sWl[dsti] = W_lin[i];
        sWs[dsti] = W_self[i];
    }
    __syncthreads();

    int o = t & 63;
    int g = t >> 6;
    float b = b_lin[o] + b_self[o] + bias[o];

    for (int tile = blockIdx.x; tile < ntiles; tile += gridDim.x) {
        int n0 = tile * 32 + g * 8;
        const float* __restrict__ xbase = x + (size_t)n0 * 64;

        if (n0 + 7 < N) {
            unsigned long long accY[8], accS[8];
            unsigned long long binit = pack_f32x2(b, 0.f);
            #pragma unroll
            for (int k = 0; k < 8; k++) { accY[k] = 0ull; accS[k] = binit; }

            #pragma unroll
            for (int f4 = 0; f4 < 16; f4++) {
                ulonglong2 wl = *reinterpret_cast<const ulonglong2*>(
                                    &sWl[f4 * 256 + o * 4]);
                ulonglong2 ws = *reinterpret_cast<const ulonglong2*>(
                                    &sWs[f4 * 256 + o * 4]);
                #pragma unroll
                for (int k = 0; k < 8; k++) {
                    ulonglong2 xv = *reinterpret_cast<const ulonglong2*>(
                                        xbase + k * 64 + f4 * 4);
                    accY[k] = fma_f32x2(xv.x, wl.x, accY[k]);
                    accY[k] = fma_f32x2(xv.y, wl.y, accY[k]);
                    accS[k] = fma_f32x2(xv.x, ws.x, accS[k]);
                    accS[k] = fma_f32x2(xv.y, ws.y, accS[k]);
                }
            }
            __half* yp = g_yh + (size_t)n0 * 64 + o;
            float* op = out + (size_t)n0 * 64 + o;
            #pragma unroll
            for (int k = 0; k < 8; k++) {
                yp[k * 64] = __float2half_rn(sum_f32x2(accY[k]));
                op[k * 64] = sum_f32x2(accS[k]);
            }
        } else {
            for (int k = 0; k < 8; k++) {
                int n = n0 + k;
                if (n >= N) break;
                float ay = 0.f, as = b;
                for (int f = 0; f < 64; f++) {
                    float xv = xbase[k * 64 + f];
                    ay += xv * sWl[(f >> 2) * 256 + o * 4 + (f & 3)];
                    as += xv * sWs[(f >> 2) * 256 + o * 4 + (f & 3)];
                }
                g_yh[(size_t)n * 64 + o] = __float2half_rn(ay);
                out[(size_t)n * 64 + o] = as;
            }
        }
    }
}

// ---------------------------------------------------------------------------
// K3: gather: out[n] += sum_slots y[slot[n][j]] (+ overflow), y in fp16.
// 8 threads/node; lane l loads 16B = 8 halves (features 8l..8l+7) per row
// with ONE LDG.128 -> total gather LDGs halved vs R13 (the binding resource).
// fp32 accumulation in 8 regs. Slot indices 4-at-a-time via broadcast
// LDG.128, prefetched a round ahead.
// ---------------------------------------------------------------------------
__global__ void __launch_bounds__(256, 4)
gather_out_kernel(float* __restrict__ out, int N) {
    const uint4* __restrict__ yh4 = (const uint4*)g_yh;   // 16B = 8 halves
    float4* __restrict__ out4 = (float4*)out;

    int idx = blockIdx.x * 256 + threadIdx.x;
    int node = idx >> 3;
    if (node >= N) return;
    int l = idx & 7;                 // 16B chunk within 128B row

    int c = g_cnt[node];
    if (c > SLOTS) c = SLOTS;
    const int4* __restrict__ sp =
        (const int4*)(g_slot + (size_t)node * SLOTS);

    float acc[8];
    #pragma unroll
    for (int k = 0; k < 8; k++) acc[k] = 0.f;

    int j = 0;
    int4 i4 = (c > 0) ? __ldg(sp) : make_int4(0, 0, 0, 0);
    for (; j + 4 <= c; j += 4) {
        int4 nx = (j + 4 < c) ? __ldg(sp + (j >> 2) + 1) : i4;
        uint4 u0 = __ldg(yh4 + (size_t)i4.x * 8 + l);
        uint4 u1 = __ldg(yh4 + (size_t)i4.y * 8 + l);
        uint4 u2 = __ldg(yh4 + (size_t)i4.z * 8 + l);
        uint4 u3 = __ldg(yh4 + (size_t)i4.w * 8 + l);

        // pairwise-sum in half2? No — convert and accumulate fp32.
        #pragma unroll
        for (int w = 0; w < 4; w++) {
            unsigned int uw0 = (&u0.x)[w];
            unsigned int uw1 = (&u1.x)[w];
            unsigned int uw2 = (&u2.x)[w];
            unsigned int uw3 = (&u3.x)[w];
            float2 f0 = __half22float2(*(__half2*)&uw0);
            float2 f1 = __half22float2(*(__half2*)&uw1);
            float2 f2 = __half22float2(*(__half2*)&uw2);
            float2 f3 = __half22float2(*(__half2*)&uw3);
            acc[w * 2 + 0] += (f0.x + f1.x) + (f2.x + f3.x);
            acc[w * 2 + 1] += (f0.y + f1.y) + (f2.y + f3.y);
        }
        i4 = nx;
    }
    // tail (0..3 edges) using the prefetched i4
    int rem = c - j;
    #pragma unroll
    for (int rIdx = 0; rIdx < 3; rIdx++) {
        if (rIdx < rem) {
            int s = (&i4.x)[rIdx];
            uint4 u = __ldg(yh4 + (size_t)s * 8 + l);
            #pragma unroll
            for (int w = 0; w < 4; w++) {
                unsigned int uw = (&u.x)[w];
                float2 f = __half22float2(*(__half2*)&uw);
                acc[w * 2 + 0] += f.x;
                acc[w * 2 + 1] += f.y;
            }
        }
    }

    // overflow entries (expected 0)
    int oc = g_ov_cnt;
    if (oc > OV_MAX) oc = OV_MAX;
    for (int k = 0; k < oc; k++) {
        if (g_ov_dst[k] == node) {
            int s = g_ov_src[k];
            uint4 u = __ldg(yh4 + (size_t)s * 8 + l);
            #pragma unroll
            for (int w = 0; w < 4; w++) {
                unsigned int uw = (&u.x)[w];
                float2 f = __half22float2(*(__half2*)&uw);
                acc[w * 2 + 0] += f.x;
                acc[w * 2 + 1] += f.y;
            }
        }
    }

    // out row: 8 fp32 features at offset l*8 -> two float4 stores
    size_t obase = (size_t)node * 16 + l * 2;
    float4 c0 = out4[obase];
    float4 c1 = out4[obase + 1];
    c0.x += acc[0]; c0.y += acc[1]; c0.z += acc[2]; c0.w += acc[3];
    c1.x += acc[4]; c1.y += acc[5]; c1.z += acc[6]; c1.w += acc[7];
    out4[obase] = c0;
    out4[obase + 1] = c1;
}

// ---------------------------------------------------------------------------
// Launch. Input order: x, src, dst, W_lin, b_lin, W_self, b_self, bias
// ---------------------------------------------------------------------------
extern "C" void kernel_launch(void* const* d_in, const int* in_sizes, int n_in,
                              void* d_out, int out_size) {
    const float* x      = (const float*)d_in[0];
    const int*   src    = (const int*)d_in[1];
    const int*   dst    = (const int*)d_in[2];
    const float* W_lin  = (const float*)d_in[3];
    const float* b_lin  = (const float*)d_in[4];
    const float* W_self = (const float*)d_in[5];
    const float* b_self = (const float*)d_in[6];
    const float* bias   = (const float*)d_in[7];
    float* out = (float*)d_out;

    int N = in_sizes[0] / IN_F;   // 100000
    int E = in_sizes[1];          // 1280000
    int ntiles = (N + 31) / 32;   // 3125

    int dev = 0, sms = 148, occ1 = 4;
    cudaGetDevice(&dev);
    cudaDeviceGetAttribute(&sms, cudaDevAttrMultiProcessorCount, dev);

    // K1: zero + single-pass bucket fill
    cudaOccupancyMaxActiveBlocksPerMultiprocessor(&occ1, bucket_fill_kernel,
                                                  256, 0);
    if (occ1 > 8) occ1 = 8;
    if (occ1 < 1) occ1 = 1;
    bucket_fill_kernel<<<sms * occ1, 256>>>(src, dst, N, E);

    // K2: GEMM
    int g2 = sms * 3;
    if (g2 > ntiles) g2 = ntiles;
    gemm_kernel<<<g2, 256>>>(x, W_lin, b_lin, W_self, b_self, bias, out,
                             N, ntiles);

    // K3: gather (8 threads per node)
    long long gt = (long long)N * 8;
    gather_out_kernel<<<(int)((gt + 255) / 256), 256>>>(out, N);
}

// round 15
// speedup vs baseline: 1.6896x; 1.1832x over previous
#include <cuda_runtime.h>
#include <cuda_fp16.h>
#include <cuda_bf16.h>

#define N_NODES 100000
#define IN_F 64
#define SLOTS 32
#define OV_MAX 4096

// Scratch
__device__ int g_cnt[N_NODES];                    // per-node fill count
__device__ int g_slot[(size_t)N_NODES * SLOTS];   // bucketed src ids (12.8MB)
__device__ int g_ov_cnt;
__device__ int g_ov_dst[OV_MAX];
__device__ int g_ov_src[OV_MAX];
__device__ __half g_yh[(size_t)N_NODES * 64];     // y = x @ W_lin^T, fp16 (12.8MB)

// Grid barrier (sense-reversing, replay-safe)
__device__ int g_bar_cnt;
__device__ volatile int g_bar_gen;

__device__ __forceinline__ void grid_bar(int nb) {
    __threadfence();
    __syncthreads();
    if (threadIdx.x == 0) {
        int gen = g_bar_gen;
        if (atomicAdd(&g_bar_cnt, 1) == nb - 1) {
            g_bar_cnt = 0;
            __threadfence();
            g_bar_gen = gen + 1;
        } else {
            while (g_bar_gen == gen) __nanosleep(32);
        }
    }
    __syncthreads();
}

// ---------------------------------------------------------------------------
// Packed f32x2 FMA (Blackwell FFMA2 — PTX only)
// ---------------------------------------------------------------------------
__device__ __forceinline__ unsigned long long fma_f32x2(unsigned long long a,
                                                        unsigned long long b,
                                                        unsigned long long c) {
    unsigned long long d;
    asm("fma.rn.f32x2 %0, %1, %2, %3;" : "=l"(d) : "l"(a), "l"(b), "l"(c));
    return d;
}
__device__ __forceinline__ unsigned long long pack_f32x2(float lo, float hi) {
    unsigned long long r;
    asm("mov.b64 %0, {%1, %2};" : "=l"(r) : "f"(lo), "f"(hi));
    return r;
}
__device__ __forceinline__ float sum_f32x2(unsigned long long v) {
    float lo, hi;
    asm("mov.b64 {%0, %1}, %2;" : "=f"(lo), "=f"(hi) : "l"(v));
    return lo + hi;
}

// ---------------------------------------------------------------------------
// K1: zero counters, then single-pass bucket fill (int4 edge loads).
// ---------------------------------------------------------------------------
__global__ void __launch_bounds__(256)
bucket_fill_kernel(const int* __restrict__ src,
                   const int* __restrict__ dst,
                   int N, int E) {
    const int t = threadIdx.x;
    const int bid = blockIdx.x;
    const int grid = gridDim.x;

    // zero counts (int4) + overflow cursor
    {
        int4* z4 = (int4*)g_cnt;
        int n4 = N >> 2;
        int4 zero = make_int4(0, 0, 0, 0);
        for (int i = bid * 256 + t; i < n4; i += grid * 256) z4[i] = zero;
        for (int i = (n4 << 2) + bid * 256 + t; i < N; i += grid * 256)
            g_cnt[i] = 0;
        if (bid == 0 && t == 0) g_ov_cnt = 0;
    }
    grid_bar(grid);

    // single fill pass
    const int E4 = E >> 2;
    const int4* dst4 = (const int4*)dst;
    const int4* src4 = (const int4*)src;
    for (int q = bid * 256 + t; q < E4; q += grid * 256) {
        int4 d = __ldg(dst4 + q);
        int4 s = __ldg(src4 + q);
        int p0 = atomicAdd(g_cnt + d.x, 1);
        int p1 = atomicAdd(g_cnt + d.y, 1);
        int p2 = atomicAdd(g_cnt + d.z, 1);
        int p3 = atomicAdd(g_cnt + d.w, 1);
        if (p0 < SLOTS) g_slot[(size_t)d.x * SLOTS + p0] = s.x;
        else { int o = atomicAdd(&g_ov_cnt, 1); if (o < OV_MAX) { g_ov_dst[o] = d.x; g_ov_src[o] = s.x; } }
        if (p1 < SLOTS) g_slot[(size_t)d.y * SLOTS + p1] = s.y;
        else { int o = atomicAdd(&g_ov_cnt, 1); if (o < OV_MAX) { g_ov_dst[o] = d.y; g_ov_src[o] = s.y; } }
        if (p2 < SLOTS) g_slot[(size_t)d.z * SLOTS + p2] = s.z;
        else { int o = atomicAdd(&g_ov_cnt, 1); if (o < OV_MAX) { g_ov_dst[o] = d.z; g_ov_src[o] = s.z; } }
        if (p3 < SLOTS) g_slot[(size_t)d.w * SLOTS + p3] = s.w;
        else { int o = atomicAdd(&g_ov_cnt, 1); if (o < OV_MAX) { g_ov_dst[o] = d.w; g_ov_src[o] = s.w; } }
    }
    for (int e = (E4 << 2) + bid * 256 + t; e < E; e += grid * 256) {
        int d = __ldg(dst + e);
        int s = __ldg(src + e);
        int p = atomicAdd(g_cnt + d, 1);
        if (p < SLOTS) g_slot[(size_t)d * SLOTS + p] = s;
        else { int o = atomicAdd(&g_ov_cnt, 1); if (o < OV_MAX) { g_ov_dst[o] = d; g_ov_src[o] = s; } }
    }
}

// ---------------------------------------------------------------------------
// K2: y = x @ W_lin^T (stored fp16) ; out = x @ W_self^T + b (fp32).
// x tile (32 nodes, 8KB) staged in smem: replaces 128 broadcast LDG.128 per
// thread per tile with LDS.128 (rt 2/SMSP vs 1.82 cyc/SM) — removes the
// LSU-issue bottleneck.
// ---------------------------------------------------------------------------
__global__ void __launch_bounds__(256, 3)
gemm_kernel(const float* __restrict__ x,
            const float* __restrict__ W_lin,
            const float* __restrict__ b_lin,
            const float* __restrict__ W_self,
            const float* __restrict__ b_self,
            const float* __restrict__ bias,
            float* __restrict__ out,
            int N, int ntiles) {
    __shared__ float sWl[64 * 64];   // [f4][o][4]
    __shared__ float sWs[64 * 64];
    __shared__ float sX[32 * 64];    // x tile (8KB)

    const int t = threadIdx.x;

    #pragma unroll
    for (int i = t; i < 64 * 64; i += 256) {
        int o = i >> 6;
        int f = i & 63;
        int dsti = (f >> 2) * 256 + o * 4 + (f & 3);
        sWl[dsti] = W_lin[i];
        sWs[dsti] = W_self[i];
    }
    __syncthreads();

    int o = t & 63;
    int g = t >> 6;
    float b = b_lin[o] + b_self[o] + bias[o];

    for (int tile = blockIdx.x; tile < ntiles; tile += gridDim.x) {
        int tn0 = tile * 32;

        // stage x tile: 512 float4 loads, coalesced
        {
            const float4* xt4 = (const float4*)(x + (size_t)tn0 * 64);
            float4* sX4 = (float4*)sX;
            int lim = (N - tn0) * 16;          // float4s available
            if (lim > 512) lim = 512;
            if (t < lim) sX4[t] = __ldg(xt4 + t);
            int t2 = t + 256;
            if (t2 < lim) sX4[t2] = __ldg(xt4 + t2);
        }
        __syncthreads();

        int n0 = tn0 + g * 8;
        const float* __restrict__ xbase = sX + g * 8 * 64;

        if (n0 + 7 < N) {
            unsigned long long accY[8], accS[8];
            unsigned long long binit = pack_f32x2(b, 0.f);
            #pragma unroll
            for (int k = 0; k < 8; k++) { accY[k] = 0ull; accS[k] = binit; }

            #pragma unroll
            for (int f4 = 0; f4 < 16; f4++) {
                ulonglong2 wl = *reinterpret_cast<const ulonglong2*>(
                                    &sWl[f4 * 256 + o * 4]);
                ulonglong2 ws = *reinterpret_cast<const ulonglong2*>(
                                    &sWs[f4 * 256 + o * 4]);
                #pragma unroll
                for (int k = 0; k < 8; k++) {
                    ulonglong2 xv = *reinterpret_cast<const ulonglong2*>(
                                        xbase + k * 64 + f4 * 4);
                    accY[k] = fma_f32x2(xv.x, wl.x, accY[k]);
                    accY[k] = fma_f32x2(xv.y, wl.y, accY[k]);
                    accS[k] = fma_f32x2(xv.x, ws.x, accS[k]);
                    accS[k] = fma_f32x2(xv.y, ws.y, accS[k]);
                }
            }
            __half* yp = g_yh + (size_t)n0 * 64 + o;
            float* op = out + (size_t)n0 * 64 + o;
            #pragma unroll
            for (int k = 0; k < 8; k++) {
                yp[k * 64] = __float2half_rn(sum_f32x2(accY[k]));
                op[k * 64] = sum_f32x2(accS[k]);
            }
        } else {
            for (int k = 0; k < 8; k++) {
                int n = n0 + k;
                if (n >= N) break;
                float ay = 0.f, as = b;
                for (int f = 0; f < 64; f++) {
                    float xv = xbase[k * 64 + f];
                    ay += xv * sWl[(f >> 2) * 256 + o * 4 + (f & 3)];
                    as += xv * sWs[(f >> 2) * 256 + o * 4 + (f & 3)];
                }
                g_yh[(size_t)n * 64 + o] = __float2half_rn(ay);
                out[(size_t)n * 64 + o] = as;
            }
        }
        __syncthreads();   // protect sX before next tile's staging
    }
}

// ---------------------------------------------------------------------------
// K3: gather: out[n] += sum_slots y[slot[n][j]] (+ overflow), y in fp16.
// 8 threads/node; lane l loads 16B = 8 halves via ONE LDG.128 per edge-row.
// fp32 accumulation. Slot indices 4-at-a-time, prefetched a round ahead.
// ---------------------------------------------------------------------------
__global__ void __launch_bounds__(256, 4)
gather_out_kernel(float* __restrict__ out, int N) {
    const uint4* __restrict__ yh4 = (const uint4*)g_yh;   // 16B = 8 halves
    float4* __restrict__ out4 = (float4*)out;

    int idx = blockIdx.x * 256 + threadIdx.x;
    int node = idx >> 3;
    if (node >= N) return;
    int l = idx & 7;                 // 16B chunk within 128B row

    int c = g_cnt[node];
    if (c > SLOTS) c = SLOTS;
    const int4* __restrict__ sp =
        (const int4*)(g_slot + (size_t)node * SLOTS);

    float acc[8];
    #pragma unroll
    for (int k = 0; k < 8; k++) acc[k] = 0.f;

    int j = 0;
    int4 i4 = (c > 0) ? __ldg(sp) : make_int4(0, 0, 0, 0);
    for (; j + 4 <= c; j += 4) {
        int4 nx = (j + 4 < c) ? __ldg(sp + (j >> 2) + 1) : i4;
        uint4 u0 = __ldg(yh4 + (size_t)i4.x * 8 + l);
        uint4 u1 = __ldg(yh4 + (size_t)i4.y * 8 + l);
        uint4 u2 = __ldg(yh4 + (size_t)i4.z * 8 + l);
        uint4 u3 = __ldg(yh4 + (size_t)i4.w * 8 + l);

        #pragma unroll
        for (int w = 0; w < 4; w++) {
            unsigned int uw0 = (&u0.x)[w];
            unsigned int uw1 = (&u1.x)[w];
            unsigned int uw2 = (&u2.x)[w];
            unsigned int uw3 = (&u3.x)[w];
            float2 f0 = __half22float2(*(__half2*)&uw0);
            float2 f1 = __half22float2(*(__half2*)&uw1);
            float2 f2 = __half22float2(*(__half2*)&uw2);
            float2 f3 = __half22float2(*(__half2*)&uw3);
            acc[w * 2 + 0] += (f0.x + f1.x) + (f2.x + f3.x);
            acc[w * 2 + 1] += (f0.y + f1.y) + (f2.y + f3.y);
        }
        i4 = nx;
    }
    // tail (0..3 edges) using the prefetched i4
    int rem = c - j;
    #pragma unroll
    for (int rIdx = 0; rIdx < 3; rIdx++) {
        if (rIdx < rem) {
            int s = (&i4.x)[rIdx];
            uint4 u = __ldg(yh4 + (size_t)s * 8 + l);
            #pragma unroll
            for (int w = 0; w < 4; w++) {
                unsigned int uw = (&u.x)[w];
                float2 f = __half22float2(*(__half2*)&uw);
                acc[w * 2 + 0] += f.x;
                acc[w * 2 + 1] += f.y;
            }
        }
    }

    // overflow entries (expected 0)
    int oc = g_ov_cnt;
    if (oc > OV_MAX) oc = OV_MAX;
    for (int k = 0; k < oc; k++) {
        if (g_ov_dst[k] == node) {
            int s = g_ov_src[k];
            uint4 u = __ldg(yh4 + (size_t)s * 8 + l);
            #pragma unroll
            for (int w = 0; w < 4; w++) {
                unsigned int uw = (&u.x)[w];
                float2 f = __half22float2(*(__half2*)&uw);
                acc[w * 2 + 0] += f.x;
                acc[w * 2 + 1] += f.y;
            }
        }
    }

    // out row: 8 fp32 features at offset l*8 -> two float4 RMWs
    size_t obase = (size_t)node * 16 + l * 2;
    float4 c0 = out4[obase];
    float4 c1 = out4[obase + 1];
    c0.x += acc[0]; c0.y += acc[1]; c0.z += acc[2]; c0.w += acc[3];
    c1.x += acc[4]; c1.y += acc[5]; c1.z += acc[6]; c1.w += acc[7];
    out4[obase] = c0;
    out4[obase + 1] = c1;
}

// ---------------------------------------------------------------------------
// Launch. Input order: x, src, dst, W_lin, b_lin, W_self, b_self, bias
// ---------------------------------------------------------------------------
extern "C" void kernel_launch(void* const* d_in, const int* in_sizes, int n_in,
                              void* d_out, int out_size) {
    const float* x      = (const float*)d_in[0];
    const int*   src    = (const int*)d_in[1];
    const int*   dst    = (const int*)d_in[2];
    const float* W_lin  = (const float*)d_in[3];
    const float* b_lin  = (const float*)d_in[4];
    const float* W_self = (const float*)d_in[5];
    const float* b_self = (const float*)d_in[6];
    const float* bias   = (const float*)d_in[7];
    float* out = (float*)d_out;

    int N = in_sizes[0] / IN_F;   // 100000
    int E = in_sizes[1];          // 1280000
    int ntiles = (N + 31) / 32;   // 3125

    int dev = 0, sms = 148, occ1 = 4;
    cudaGetDevice(&dev);
    cudaDeviceGetAttribute(&sms, cudaDevAttrMultiProcessorCount, dev);

    // K1: zero + single-pass bucket fill
    cudaOccupancyMaxActiveBlocksPerMultiprocessor(&occ1, bucket_fill_kernel,
                                                  256, 0);
    if (occ1 > 8) occ1 = 8;
    if (occ1 < 1) occ1 = 1;
    bucket_fill_kernel<<<sms * occ1, 256>>>(src, dst, N, E);

    // K2: GEMM
    int g2 = sms * 3;
    if (g2 > ntiles) g2 = ntiles;
    gemm_kernel<<<g2, 256>>>(x, W_lin, b_lin, W_self, b_self, bias, out,
                             N, ntiles);

    // K3: gather (8 threads per node)
    long long gt = (long long)N * 8;
    gather_out_kernel<<<(int)((gt + 255) / 256), 256>>>(out, N);
}